// round 4
// baseline (speedup 1.0000x reference)
#include <cuda_runtime.h>
#include <cuda_bf16.h>

#define C    256
#define H    200
#define W    200
#define HP   201    // H + 1 (padded integral image)
#define WP   201
#define NBOX 1024
#define OH   7
#define OW   7

// Scratch: transposed feature map [y][x][c] and integral image [r][col][c] (channel-innermost)
__device__ float g_fmT[H * W * C];          // 40.96 MB
__device__ float g_iiT[HP * WP * C];        // 41.37 MB

// ---------------------------------------------------------------------------
// Kernel 1: zero the r==0 row and col==0 column of the integral image.
// ---------------------------------------------------------------------------
__global__ void init_border_kernel() {
    int idx = blockIdx.x * blockDim.x + threadIdx.x;
    const int row0 = WP * C;                // (0, col, c) for all col, c
    const int col0 = (HP - 1) * C;          // (r, 0, c) for r = 1..200
    if (idx < row0) {
        g_iiT[idx] = 0.0f;
    } else if (idx < row0 + col0) {
        int k = idx - row0;
        int r = k / C + 1;
        int c = k % C;
        g_iiT[(r * WP + 0) * C + c] = 0.0f;
    }
}

// ---------------------------------------------------------------------------
// Kernel 2: transpose fm [C][H*W] -> fmT [H*W][C] via 32x32 smem tiles.
// ---------------------------------------------------------------------------
__global__ void transpose_kernel(const float* __restrict__ fm) {
    __shared__ float tile[32][33];
    const int P = H * W;                    // 40000, divisible by 32
    int p0 = blockIdx.x * 32;
    int c0 = blockIdx.y * 32;
    int tx = threadIdx.x;                   // 0..31
    int ty = threadIdx.y;                   // 0..7
#pragma unroll
    for (int k = 0; k < 4; k++) {
        int c = c0 + ty + k * 8;
        int p = p0 + tx;
        tile[ty + k * 8][tx] = fm[c * P + p];
    }
    __syncthreads();
#pragma unroll
    for (int k = 0; k < 4; k++) {
        int p = p0 + ty + k * 8;
        int c = c0 + tx;
        g_fmT[p * C + c] = tile[tx][ty + k * 8];
    }
}

// ---------------------------------------------------------------------------
// Kernel 3: cumulative sum over y. One thread per (x, c) pair; c innermost so
// every warp load/store is a contiguous 128B line.
// Writes into iiT at (y+1, x+1) — column sums, pre x-scan.
// ---------------------------------------------------------------------------
__global__ void scan_y_kernel() {
    int idx = blockIdx.x * blockDim.x + threadIdx.x;  // over W*C = 51200
    if (idx >= W * C) return;
    int x = idx / C;
    int c = idx % C;
    float run = 0.0f;
#pragma unroll 4
    for (int y = 0; y < H; y++) {
        run += g_fmT[(y * W + x) * C + c];
        g_iiT[((y + 1) * WP + (x + 1)) * C + c] = run;
    }
}

// ---------------------------------------------------------------------------
// Kernel 4: in-place cumulative sum over x. One thread per (y, c) pair.
// ---------------------------------------------------------------------------
__global__ void scan_x_kernel() {
    int idx = blockIdx.x * blockDim.x + threadIdx.x;  // over H*C = 51200
    if (idx >= H * C) return;
    int y = idx / C + 1;                    // rows 1..200
    int c = idx % C;
    float run = 0.0f;
#pragma unroll 4
    for (int x = 1; x <= W; x++) {
        int off = (y * WP + x) * C + c;
        run += g_iiT[off];
        g_iiT[off] = run;
    }
}

// ---------------------------------------------------------------------------
// Kernel 5: ROI pooling output. One block per box, one thread per channel.
// Bin edges + reciprocal areas in smem; 4 coalesced gathers per bin.
// ---------------------------------------------------------------------------
__global__ void __launch_bounds__(C) roi_output_kernel(
    const float* __restrict__ boxes, float* __restrict__ out)
{
    const int n = blockIdx.x;
    const int c = threadIdx.x;

    __shared__ int   s_rs[OH], s_re[OH], s_cs[OW], s_ce[OW];
    __shared__ float s_inv_area[OH * OW];

    // Threads 0..6 compute bin edges (each re-derives box coords; cached loads).
    if (c < OH) {
        const float sc = 0.25f;  // W/IMG_W = H/IMG_H = 200/800, exact in fp32
        int bx1 = (int)floorf(boxes[n * 4 + 0] * sc);
        int by1 = (int)floorf(boxes[n * 4 + 1] * sc);
        int bx2 = (int)floorf(boxes[n * 4 + 2] * sc);
        int by2 = (int)floorf(boxes[n * 4 + 3] * sc);
        int x1 = min(max(bx1, 0), W - 1);
        int y1 = min(max(by1, 0), H - 1);
        int x2 = min(max(bx2 + 1, x1 + 1), W);
        int y2 = min(max(by2 + 1, y1 + 1), H);
        int rh = y2 - y1;
        int rw = x2 - x1;
        int i = c;
        s_rs[i] = y1 + (i * rh) / OH;
        s_re[i] = y1 + ((i + 1) * rh + OH - 1) / OH;
        s_cs[i] = x1 + (i * rw) / OW;
        s_ce[i] = x1 + ((i + 1) * rw + OW - 1) / OW;
    }
    __syncthreads();
    if (c < OH * OW) {
        int i = c / OW, j = c % OW;
        int area = (s_re[i] - s_rs[i]) * (s_ce[j] - s_cs[j]);
        s_inv_area[c] = 1.0f / (float)area;
    }
    __syncthreads();

    const float* ii = g_iiT + c;
    float* dst = out + ((size_t)n * C + c) * (OH * OW);

#pragma unroll
    for (int i = 0; i < OH; i++) {
        int r0 = s_rs[i] * WP;
        int r1 = s_re[i] * WP;
#pragma unroll
        for (int j = 0; j < OW; j++) {
            int c0 = s_cs[j];
            int c1 = s_ce[j];
            float s = ii[(r1 + c1) * C] - ii[(r0 + c1) * C]
                    - ii[(r1 + c0) * C] + ii[(r0 + c0) * C];
            dst[i * OW + j] = s * s_inv_area[i * OW + j];
        }
    }
}

// ---------------------------------------------------------------------------
extern "C" void kernel_launch(void* const* d_in, const int* in_sizes, int n_in,
                              void* d_out, int out_size)
{
    // Identify inputs by size: feature map has 10,240,000 elems, boxes 4096.
    const float* fm    = (const float*)d_in[0];
    const float* boxes = (const float*)d_in[1];
    if (n_in >= 2 && in_sizes[0] < in_sizes[1]) {
        fm    = (const float*)d_in[1];
        boxes = (const float*)d_in[0];
    }
    float* out = (float*)d_out;

    // 1) zero the integral-image border
    {
        int total = WP * C + (HP - 1) * C;
        int blocks = (total + 255) / 256;
        init_border_kernel<<<blocks, 256>>>();
    }
    // 2) transpose fm -> fmT (channel-innermost)
    {
        dim3 grid((H * W) / 32, C / 32);
        dim3 block(32, 8);
        transpose_kernel<<<grid, block>>>(fm);
    }
    // 3) cumsum over y
    scan_y_kernel<<<(W * C + 255) / 256, 256>>>();
    // 4) cumsum over x (in place)
    scan_x_kernel<<<(H * C + 255) / 256, 256>>>();
    // 5) ROI pooling output
    roi_output_kernel<<<NBOX, C>>>(boxes, out);
}

// round 6
// speedup vs baseline: 1.7745x; 1.7745x over previous
#include <cuda_runtime.h>
#include <cuda_bf16.h>

#define C    256
#define H    200
#define W    200
#define HP   201
#define WP   201
#define NBOX 1024
#define OH   7
#define OW   7
#define SEG  8
#define LSEG 25          // 200 / 8

// Integral image [r][col][c] (channel-innermost), partial-x-scan after xscan_kernel
__device__ float g_ii[HP * WP * C];          // 41.4 MB
// Per-y-segment column totals -> exclusive prefix (y fixup), [seg][x][c]
__device__ float g_colsum[SEG * W * C];      // 1.6 MB
// Per-x-segment row totals -> exclusive prefix (x fixup), [seg][r][c]
__device__ float g_rowsum[SEG * HP * C];     // 1.65 MB

// ---------------------------------------------------------------------------
// Zero the r==0 row and col==0 column of the integral image.
// ---------------------------------------------------------------------------
__global__ void init_border_kernel() {
    int idx = blockIdx.x * blockDim.x + threadIdx.x;
    const int row0 = WP * C;          // (0, col, c)
    const int col0 = H * C;           // (r=1..200, 0, c)
    if (idx < row0) {
        g_ii[idx] = 0.0f;
    } else if (idx < row0 + col0) {
        int k = idx - row0;
        int r = k / C + 1;
        int c = k % C;
        g_ii[(r * WP) * C + c] = 0.0f;
    }
}

// ---------------------------------------------------------------------------
// Fused transpose + segmented y-scan.
// Block: 32 x-values × 32 channels × 25 y. Reads fm [c][y][x] coalesced,
// smem-transposes, accumulates per-thread running sums, writes partial
// (within-segment) column prefix sums into g_ii, segment totals into g_colsum.
// ---------------------------------------------------------------------------
__global__ void __launch_bounds__(256) yscan_kernel(const float* __restrict__ fm) {
    __shared__ float tile[32][33];    // [c_local][x_local]
    const int x0 = blockIdx.x * 32;
    const int c0 = blockIdx.y * 32;
    const int y0 = blockIdx.z * LSEG;
    const int tx = threadIdx.x;       // 0..31
    const int ty = threadIdx.y;       // 0..7
    const int cS = c0 + tx;           // owned channel (store side)

    float run[4] = {0.f, 0.f, 0.f, 0.f};

    for (int yy = 0; yy < LSEG; yy++) {
        int y = y0 + yy;
#pragma unroll
        for (int k = 0; k < 4; k++) {
            int cl = ty + 8 * k;
            int x  = x0 + tx;
            tile[cl][tx] = (x < W) ? fm[((c0 + cl) * H + y) * W + x] : 0.f;
        }
        __syncthreads();
#pragma unroll
        for (int k = 0; k < 4; k++) {
            int xl = ty + 8 * k;
            run[k] += tile[tx][xl];
            int x = x0 + xl;
            if (x < W)
                g_ii[((y + 1) * WP + (x + 1)) * C + cS] = run[k];
        }
        __syncthreads();
    }
#pragma unroll
    for (int k = 0; k < 4; k++) {
        int x = x0 + ty + 8 * k;
        if (x < W)
            g_colsum[(blockIdx.z * W + x) * C + cS] = run[k];
    }
}

// ---------------------------------------------------------------------------
// In-place exclusive prefix over the 8 y-segment totals, per (x, c).
// ---------------------------------------------------------------------------
__global__ void colprefix_kernel() {
    int t = blockIdx.x * blockDim.x + threadIdx.x;   // t = x*C + c
    if (t >= W * C) return;
    float s = 0.f;
#pragma unroll
    for (int sg = 0; sg < SEG; sg++) {
        int off = sg * W * C + t;
        float v = g_colsum[off];
        g_colsum[off] = s;
        s += v;
    }
}

// ---------------------------------------------------------------------------
// Segmented x-scan with fused y-fixup. Thread per (x-seg, y, c):
//   run += ii_partial[r][x+1][c] + colPrefix[segy(y)][x][c]
// Writes within-segment x-prefix back, plus segment row totals.
// 409,600 threads -> ~86 warps/SM.
// ---------------------------------------------------------------------------
__global__ void __launch_bounds__(256) xscan_kernel() {
    int t  = blockIdx.x * blockDim.x + threadIdx.x;  // SEG*H*C total
    int c  = t % C;
    int y  = (t / C) % H;
    int sx = t / (C * H);
    int sy = y / LSEG;
    int r  = y + 1;
    const float* cp = g_colsum + (sy * W) * C + c;
    float run = 0.f;
    int x0 = sx * LSEG;
#pragma unroll 5
    for (int xx = 0; xx < LSEG; xx++) {
        int x   = x0 + xx;
        int off = (r * WP + (x + 1)) * C + c;
        run += g_ii[off] + cp[x * C];
        g_ii[off] = run;
    }
    g_rowsum[(sx * HP + r) * C + c] = run;
}

// ---------------------------------------------------------------------------
// In-place exclusive prefix over the 8 x-segment totals, per (r, c).
// Forces r==0 rows to zero (border).
// ---------------------------------------------------------------------------
__global__ void rowprefix_kernel() {
    int t = blockIdx.x * blockDim.x + threadIdx.x;   // t = r*C + c
    if (t >= HP * C) return;
    float s = 0.f;
#pragma unroll
    for (int sg = 0; sg < SEG; sg++) {
        int off = sg * HP * C + t;
        float v = g_rowsum[off];
        g_rowsum[off] = (t < C) ? 0.f : s;           // r==0 -> 0
        s += v;
    }
}

// ---------------------------------------------------------------------------
// ROI pooling output. One block per box, one thread per channel.
// Corner value = ii_partial(r,k) + rowPrefix(seg(k-1), r); 8 coalesced
// gathers per bin. Output staged in smem, flushed with coalesced float4.
// ---------------------------------------------------------------------------
__global__ void __launch_bounds__(C) roi_kernel(const float* __restrict__ boxes,
                                                float* __restrict__ out)
{
    extern __shared__ float s_out[];                 // C*49 floats = 50176 B
    __shared__ int   s_rs[OH], s_re[OH], s_cs[OW], s_ce[OW];
    __shared__ int   s_csSeg[OW], s_ceSeg[OW];
    __shared__ float s_inv[OH * OW];

    const int n = blockIdx.x;
    const int c = threadIdx.x;

    if (c < OH) {
        const float sc = 0.25f;                      // 200/800, exact
        int bx1 = (int)floorf(boxes[n * 4 + 0] * sc);
        int by1 = (int)floorf(boxes[n * 4 + 1] * sc);
        int bx2 = (int)floorf(boxes[n * 4 + 2] * sc);
        int by2 = (int)floorf(boxes[n * 4 + 3] * sc);
        int x1 = min(max(bx1, 0), W - 1);
        int y1 = min(max(by1, 0), H - 1);
        int x2 = min(max(bx2 + 1, x1 + 1), W);
        int y2 = min(max(by2 + 1, y1 + 1), H);
        int rh = y2 - y1, rw = x2 - x1;
        int i = c;
        s_rs[i] = y1 + (i * rh) / OH;
        s_re[i] = y1 + ((i + 1) * rh + OH - 1) / OH;
        int csv = x1 + (i * rw) / OW;
        int cev = x1 + ((i + 1) * rw + OW - 1) / OW;
        s_cs[i] = csv;
        s_ce[i] = cev;
        s_csSeg[i] = max(csv - 1, 0) / LSEG;         // cs==0 -> seg0 (prefix 0)
        s_ceSeg[i] = (cev - 1) / LSEG;               // ce >= 1 always
    }
    __syncthreads();
    if (c < OH * OW) {
        int i = c / OW, j = c % OW;
        s_inv[c] = 1.0f / (float)((s_re[i] - s_rs[i]) * (s_ce[j] - s_cs[j]));
    }
    __syncthreads();

    const float* ii = g_ii + c;
    const float* rp = g_rowsum + c;

#pragma unroll
    for (int i = 0; i < OH; i++) {
        int rA = s_rs[i], rB = s_re[i];
#pragma unroll
        for (int j = 0; j < OW; j++) {
            int kA = s_cs[j],    kB = s_ce[j];
            int sA = s_csSeg[j], sB = s_ceSeg[j];
            float v = ii[(rB * WP + kB) * C] - ii[(rA * WP + kB) * C]
                    - ii[(rB * WP + kA) * C] + ii[(rA * WP + kA) * C]
                    + rp[(sB * HP + rB) * C] - rp[(sB * HP + rA) * C]
                    - rp[(sA * HP + rB) * C] + rp[(sA * HP + rA) * C];
            s_out[c * (OH * OW) + i * OW + j] = v * s_inv[i * OW + j];
        }
    }
    __syncthreads();

    // Coalesced float4 flush: 12544 floats = 3136 float4, base 16B-aligned.
    float4*       dst = (float4*)(out + (size_t)n * C * (OH * OW));
    const float4* src = (const float4*)s_out;
    for (int idx = c; idx < (C * OH * OW) / 4; idx += C)
        dst[idx] = src[idx];
}

// ---------------------------------------------------------------------------
extern "C" void kernel_launch(void* const* d_in, const int* in_sizes, int n_in,
                              void* d_out, int out_size)
{
    const float* fm    = (const float*)d_in[0];
    const float* boxes = (const float*)d_in[1];
    if (n_in >= 2 && in_sizes[0] < in_sizes[1]) {
        fm    = (const float*)d_in[1];
        boxes = (const float*)d_in[0];
    }
    float* out = (float*)d_out;

    // roi_kernel needs 50176 B dynamic smem (> 48 KB default)
    cudaFuncSetAttribute(roi_kernel, cudaFuncAttributeMaxDynamicSharedMemorySize,
                         C * OH * OW * (int)sizeof(float));

    // 1) zero integral-image border
    {
        int total = WP * C + H * C;
        init_border_kernel<<<(total + 255) / 256, 256>>>();
    }
    // 2) fused transpose + segmented y-scan
    {
        dim3 grid((W + 31) / 32, C / 32, SEG);
        dim3 block(32, 8);
        yscan_kernel<<<grid, block>>>(fm);
    }
    // 3) y-segment exclusive prefix
    colprefix_kernel<<<(W * C + 255) / 256, 256>>>();
    // 4) segmented x-scan + fused y-fixup
    xscan_kernel<<<(SEG * H * C) / 256, 256>>>();
    // 5) x-segment exclusive prefix
    rowprefix_kernel<<<(HP * C + 255) / 256, 256>>>();
    // 6) ROI pooling output (x-fixup fused into gather)
    roi_kernel<<<NBOX, C, C * OH * OW * (int)sizeof(float)>>>(boxes, out);
}

// round 8
// speedup vs baseline: 2.0202x; 1.1384x over previous
#include <cuda_runtime.h>
#include <cuda_bf16.h>

#define C    256
#define C4   64          // C / 4
#define H    200
#define W    200
#define HP   201
#define WP   201
#define NBOX 1024
#define OH   7
#define OW   7
#define SEG  10
#define LSEG 20          // 200 / 10
#define YCH  5           // y-rows per smem chunk in yscan

// Integral image [r][col][c] (channel-innermost); partial-x-scan after xscan_kernel
__device__ float g_ii[HP * WP * C];          // 41.4 MB
// Per-y-segment column totals -> exclusive prefix (y fixup), [seg][x][c]
__device__ float g_colsum[SEG * W * C];      // 2.0 MB
// Per-x-segment row totals -> exclusive prefix (x fixup), [seg][r][c]
__device__ float g_rowsum[SEG * HP * C];     // 2.1 MB

// ---------------------------------------------------------------------------
// Zero the r==0 row and col==0 column of the integral image.
// ---------------------------------------------------------------------------
__global__ void init_border_kernel() {
    int idx = blockIdx.x * blockDim.x + threadIdx.x;
    const int row0 = WP * C;          // (0, col, c)
    const int col0 = H * C;           // (r=1..200, 0, c)
    if (idx < row0) {
        g_ii[idx] = 0.0f;
    } else if (idx < row0 + col0) {
        int k = idx - row0;
        int r = k / C + 1;
        int c = k % C;
        g_ii[(r * WP) * C + c] = 0.0f;
    }
}

// ---------------------------------------------------------------------------
// Fused transpose + segmented y-scan, chunked 5 y-rows per barrier pair.
// Block: 32 x-values x 32 channels x LSEG y. Reads fm [c][y][x] coalesced,
// smem-transposes, accumulates running sums in registers, writes partial
// column prefixes into g_ii, segment totals into g_colsum.
// ---------------------------------------------------------------------------
__global__ void __launch_bounds__(256) yscan_kernel(const float* __restrict__ fm) {
    __shared__ float tile[YCH][32][33];   // [y][c_local][x_local]
    const int x0 = blockIdx.x * 32;
    const int c0 = blockIdx.y * 32;
    const int y0 = blockIdx.z * LSEG;
    const int tx = threadIdx.x;           // 0..31
    const int ty = threadIdx.y;           // 0..7
    const int cS = c0 + tx;               // owned channel (store side)
    const bool xinL = (x0 + tx) < W;      // load-side guard

    float run[4] = {0.f, 0.f, 0.f, 0.f};

    for (int ch = 0; ch < LSEG / YCH; ch++) {
        int yb = y0 + ch * YCH;
#pragma unroll
        for (int yy = 0; yy < YCH; yy++) {
#pragma unroll
            for (int k = 0; k < 4; k++) {
                int cl = ty + 8 * k;
                tile[yy][cl][tx] =
                    xinL ? fm[((c0 + cl) * H + (yb + yy)) * W + (x0 + tx)] : 0.f;
            }
        }
        __syncthreads();
#pragma unroll
        for (int yy = 0; yy < YCH; yy++) {
            int y = yb + yy;
#pragma unroll
            for (int k = 0; k < 4; k++) {
                int xl = ty + 8 * k;
                run[k] += tile[yy][tx][xl];
                int x = x0 + xl;
                if (x < W)
                    g_ii[((y + 1) * WP + (x + 1)) * C + cS] = run[k];
            }
        }
        __syncthreads();
    }
#pragma unroll
    for (int k = 0; k < 4; k++) {
        int x = x0 + ty + 8 * k;
        if (x < W)
            g_colsum[(blockIdx.z * W + x) * C + cS] = run[k];
    }
}

// ---------------------------------------------------------------------------
// In-place exclusive prefix over the SEG y-segment totals, per (x, c4). float4.
// ---------------------------------------------------------------------------
__global__ void colprefix_kernel() {
    int t = blockIdx.x * blockDim.x + threadIdx.x;   // over W*C4
    if (t >= W * C4) return;
    float4* p = (float4*)g_colsum;
    float4 s = {0.f, 0.f, 0.f, 0.f};
#pragma unroll
    for (int sg = 0; sg < SEG; sg++) {
        int off = sg * W * C4 + t;
        float4 v = p[off];
        p[off] = s;
        s.x += v.x; s.y += v.y; s.z += v.z; s.w += v.w;
    }
}

// ---------------------------------------------------------------------------
// Segmented x-scan with fused y-fixup, float4 over channels.
// Thread per (x-seg, y, c4):
//   run += ii_partial[r][x+1][c4] + colPrefix[segy(y)][x][c4]
// Writes within-segment x-prefix back, plus segment row totals.
// SEG*H*C4 = 128,000 threads.
// ---------------------------------------------------------------------------
__global__ void __launch_bounds__(256) xscan_kernel() {
    int t  = blockIdx.x * blockDim.x + threadIdx.x;
    int c4 = t & (C4 - 1);
    int y  = (t >> 6) % H;
    int sx = t / (C4 * H);
    int sy = y / LSEG;
    int r  = y + 1;
    float4* ii = (float4*)g_ii;
    const float4* cp = (const float4*)g_colsum + (sy * W) * C4 + c4;
    float4 run = {0.f, 0.f, 0.f, 0.f};
    int x0 = sx * LSEG;
#pragma unroll 5
    for (int xx = 0; xx < LSEG; xx++) {
        int x   = x0 + xx;
        int off = (r * WP + (x + 1)) * C4 + c4;
        float4 v = ii[off];
        float4 a = cp[x * C4];
        run.x += v.x + a.x;
        run.y += v.y + a.y;
        run.z += v.z + a.z;
        run.w += v.w + a.w;
        ii[off] = run;
    }
    ((float4*)g_rowsum)[(sx * HP + r) * C4 + c4] = run;
}

// ---------------------------------------------------------------------------
// In-place exclusive prefix over the SEG x-segment totals, per (r, c4).
// Forces r==0 rows to zero (border). float4.
// ---------------------------------------------------------------------------
__global__ void rowprefix_kernel() {
    int t = blockIdx.x * blockDim.x + threadIdx.x;   // over HP*C4
    if (t >= HP * C4) return;
    float4* p = (float4*)g_rowsum;
    const float4 z = {0.f, 0.f, 0.f, 0.f};
    float4 s = z;
#pragma unroll
    for (int sg = 0; sg < SEG; sg++) {
        int off = sg * HP * C4 + t;
        float4 v = p[off];
        p[off] = (t < C4) ? z : s;                   // r==0 -> 0
        s.x += v.x; s.y += v.y; s.z += v.z; s.w += v.w;
    }
}

// ---------------------------------------------------------------------------
// ROI pooling output. One block per box, one thread per channel.
// Full corner value = ii_partial(r,k) + rowPrefix(seg(k), r); 8 coalesced
// gathers per bin. Output staged in smem, flushed with coalesced float4.
// ---------------------------------------------------------------------------
__global__ void __launch_bounds__(C) roi_kernel(const float* __restrict__ boxes,
                                                float* __restrict__ out)
{
    extern __shared__ float s_out[];                 // C*49 floats = 50176 B
    __shared__ int   s_rs[OH], s_re[OH], s_cs[OW], s_ce[OW];
    __shared__ int   s_csSeg[OW], s_ceSeg[OW];
    __shared__ float s_inv[OH * OW];

    const int n = blockIdx.x;
    const int c = threadIdx.x;

    if (c < OH) {
        const float sc = 0.25f;                      // 200/800, exact in fp32
        int bx1 = (int)floorf(boxes[n * 4 + 0] * sc);
        int by1 = (int)floorf(boxes[n * 4 + 1] * sc);
        int bx2 = (int)floorf(boxes[n * 4 + 2] * sc);
        int by2 = (int)floorf(boxes[n * 4 + 3] * sc);
        int x1 = min(max(bx1, 0), W - 1);
        int y1 = min(max(by1, 0), H - 1);
        int x2 = min(max(bx2 + 1, x1 + 1), W);
        int y2 = min(max(by2 + 1, y1 + 1), H);
        int rh = y2 - y1, rw = x2 - x1;
        int i = c;
        s_rs[i] = y1 + (i * rh) / OH;
        s_re[i] = y1 + ((i + 1) * rh + OH - 1) / OH;
        int csv = x1 + (i * rw) / OW;
        int cev = x1 + ((i + 1) * rw + OW - 1) / OW;
        s_cs[i] = csv;
        s_ce[i] = cev;
        s_csSeg[i] = max(csv - 1, 0) / LSEG;         // cs==0 -> seg0 (prefix 0)
        s_ceSeg[i] = (cev - 1) / LSEG;               // ce >= 1 always
    }
    __syncthreads();
    if (c < OH * OW) {
        int i = c / OW, j = c % OW;
        s_inv[c] = 1.0f / (float)((s_re[i] - s_rs[i]) * (s_ce[j] - s_cs[j]));
    }
    __syncthreads();

    const float* ii = g_ii + c;
    const float* rp = g_rowsum + c;

#pragma unroll
    for (int i = 0; i < OH; i++) {
        int rA = s_rs[i], rB = s_re[i];
#pragma unroll
        for (int j = 0; j < OW; j++) {
            int kA = s_cs[j],    kB = s_ce[j];
            int sA = s_csSeg[j], sB = s_ceSeg[j];
            float v = ii[(rB * WP + kB) * C] - ii[(rA * WP + kB) * C]
                    - ii[(rB * WP + kA) * C] + ii[(rA * WP + kA) * C]
                    + rp[(sB * HP + rB) * C] - rp[(sB * HP + rA) * C]
                    - rp[(sA * HP + rB) * C] + rp[(sA * HP + rA) * C];
            s_out[c * (OH * OW) + i * OW + j] = v * s_inv[i * OW + j];
        }
    }
    __syncthreads();

    // Coalesced float4 flush: 12544 floats = 3136 float4, base 16B-aligned.
    float4*       dst = (float4*)(out + (size_t)n * C * (OH * OW));
    const float4* src = (const float4*)s_out;
    for (int idx = c; idx < (C * OH * OW) / 4; idx += C)
        dst[idx] = src[idx];
}

// ---------------------------------------------------------------------------
extern "C" void kernel_launch(void* const* d_in, const int* in_sizes, int n_in,
                              void* d_out, int out_size)
{
    const float* fm    = (const float*)d_in[0];
    const float* boxes = (const float*)d_in[1];
    if (n_in >= 2 && in_sizes[0] < in_sizes[1]) {
        fm    = (const float*)d_in[1];
        boxes = (const float*)d_in[0];
    }
    float* out = (float*)d_out;

    // roi_kernel needs 50176 B dynamic smem (> 48 KB default)
    cudaFuncSetAttribute(roi_kernel, cudaFuncAttributeMaxDynamicSharedMemorySize,
                         C * OH * OW * (int)sizeof(float));

    // 1) zero integral-image border
    {
        int total = WP * C + H * C;
        init_border_kernel<<<(total + 255) / 256, 256>>>();
    }
    // 2) fused transpose + segmented y-scan (chunked barriers)
    {
        dim3 grid((W + 31) / 32, C / 32, SEG);
        dim3 block(32, 8);
        yscan_kernel<<<grid, block>>>(fm);
    }
    // 3) y-segment exclusive prefix (float4)
    colprefix_kernel<<<(W * C4 + 255) / 256, 256>>>();
    // 4) segmented x-scan + fused y-fixup (float4)
    xscan_kernel<<<(SEG * H * C4) / 256, 256>>>();
    // 5) x-segment exclusive prefix (float4)
    rowprefix_kernel<<<(HP * C4 + 255) / 256, 256>>>();
    // 6) ROI pooling output (x-fixup fused into gather)
    roi_kernel<<<NBOX, C, C * OH * OW * (int)sizeof(float)>>>(boxes, out);
}

// round 10
// speedup vs baseline: 2.6566x; 1.3150x over previous
#include <cuda_runtime.h>
#include <cuda_bf16.h>

#define C    256
#define C4   64          // C / 4
#define H    200
#define W    200
#define HP   201
#define WP   201
#define NBOX 1024
#define OH   7
#define OW   7
#define SEG  20          // segments for BOTH y-scan and x-scan
#define LSEG 10          // 200 / 20
#define YCH  5           // y-rows per smem chunk in yscan (2 chunks per segment)

// Integral image [r][col][c] (channel-innermost); partial-x-scan after xscan_kernel
__device__ float g_ii[HP * WP * C];          // 41.4 MB
// Per-y-segment column totals -> exclusive prefix (y fixup), [seg][x][c]
__device__ float g_colsum[SEG * W * C];      // 4.1 MB
// Per-x-segment row totals -> exclusive prefix (x fixup), [seg][r][c]
__device__ float g_rowsum[SEG * HP * C];     // 4.1 MB

// ---------------------------------------------------------------------------
// Fused transpose + segmented y-scan. grid = (7, 8, SEG); block 32x8.
// Each segment scans LSEG=10 y-rows; 2 smem chunks of 5 rows -> 4 barriers.
// Reads fm [c][y][x] coalesced, smem-transposes, register running sums,
// writes partial column prefixes into g_ii, segment totals into g_colsum.
// ---------------------------------------------------------------------------
__global__ void __launch_bounds__(256) yscan_kernel(const float* __restrict__ fm) {
    __shared__ float tile[YCH][32][33];   // [y][c_local][x_local]
    const int x0 = blockIdx.x * 32;
    const int c0 = blockIdx.y * 32;
    const int y0 = blockIdx.z * LSEG;
    const int tx = threadIdx.x;           // 0..31
    const int ty = threadIdx.y;           // 0..7
    const int cS = c0 + tx;               // owned channel (store side)
    const bool xinL = (x0 + tx) < W;      // load-side guard

    float run[4] = {0.f, 0.f, 0.f, 0.f};

#pragma unroll
    for (int ch = 0; ch < LSEG / YCH; ch++) {
        int yb = y0 + ch * YCH;
#pragma unroll
        for (int yy = 0; yy < YCH; yy++) {
#pragma unroll
            for (int k = 0; k < 4; k++) {
                int cl = ty + 8 * k;
                tile[yy][cl][tx] =
                    xinL ? fm[((c0 + cl) * H + (yb + yy)) * W + (x0 + tx)] : 0.f;
            }
        }
        __syncthreads();
#pragma unroll
        for (int yy = 0; yy < YCH; yy++) {
            int y = yb + yy;
#pragma unroll
            for (int k = 0; k < 4; k++) {
                int xl = ty + 8 * k;
                run[k] += tile[yy][tx][xl];
                int x = x0 + xl;
                if (x < W)
                    g_ii[((y + 1) * WP + (x + 1)) * C + cS] = run[k];
            }
        }
        __syncthreads();
    }
#pragma unroll
    for (int k = 0; k < 4; k++) {
        int x = x0 + ty + 8 * k;
        if (x < W)
            g_colsum[(blockIdx.z * W + x) * C + cS] = run[k];
    }
}

// ---------------------------------------------------------------------------
// In-place exclusive prefix over the SEG y-segment totals, per (x, c4). float4.
// ---------------------------------------------------------------------------
__global__ void colprefix_kernel() {
    int t = blockIdx.x * blockDim.x + threadIdx.x;   // over W*C4
    if (t >= W * C4) return;
    float4* p = (float4*)g_colsum;
    float4 s = {0.f, 0.f, 0.f, 0.f};
#pragma unroll
    for (int sg = 0; sg < SEG; sg++) {
        int off = sg * W * C4 + t;
        float4 v = p[off];
        p[off] = s;
        s.x += v.x; s.y += v.y; s.z += v.z; s.w += v.w;
    }
}

// ---------------------------------------------------------------------------
// Segmented x-scan with fused y-fixup, float4 over channels.
// Thread per (x-seg, y, c4); chain length LSEG=10.
// SEG*H*C4 = 256,000 threads (~54 warps/SM).
// ---------------------------------------------------------------------------
__global__ void __launch_bounds__(256) xscan_kernel() {
    int t  = blockIdx.x * blockDim.x + threadIdx.x;
    int c4 = t & (C4 - 1);
    int y  = (t >> 6) % H;
    int sx = t / (C4 * H);
    int sy = y / LSEG;
    int r  = y + 1;
    float4* ii = (float4*)g_ii;
    const float4* cp = (const float4*)g_colsum + (sy * W) * C4 + c4;
    float4 run = {0.f, 0.f, 0.f, 0.f};
    int x0 = sx * LSEG;
#pragma unroll 5
    for (int xx = 0; xx < LSEG; xx++) {
        int x   = x0 + xx;
        int off = (r * WP + (x + 1)) * C4 + c4;
        float4 v = ii[off];
        float4 a = cp[x * C4];
        run.x += v.x + a.x;
        run.y += v.y + a.y;
        run.z += v.z + a.z;
        run.w += v.w + a.w;
        ii[off] = run;
    }
    ((float4*)g_rowsum)[(sx * HP + r) * C4 + c4] = run;
}

// ---------------------------------------------------------------------------
// Fused: (a) in-place exclusive prefix over SEG x-segment totals per (r, c4),
// forcing r==0 to zero; (b) zero the r==0 row and k==0 column of g_ii.
// ---------------------------------------------------------------------------
__global__ void rowprefix_border_kernel() {
    int t = blockIdx.x * blockDim.x + threadIdx.x;
    const int nPfx  = HP * C4;        // prefix work items
    const int nRow0 = WP * C4;        // ii row r==0 (float4)
    const int nCol0 = H * C4;         // ii col k==0, r=1..200 (float4)
    if (t < nPfx) {
        float4* p = (float4*)g_rowsum;
        const float4 z = {0.f, 0.f, 0.f, 0.f};
        float4 s = z;
#pragma unroll
        for (int sg = 0; sg < SEG; sg++) {
            int off = sg * HP * C4 + t;
            float4 v = p[off];
            p[off] = (t < C4) ? z : s;               // r==0 -> 0
            s.x += v.x; s.y += v.y; s.z += v.z; s.w += v.w;
        }
    } else if (t < nPfx + nRow0) {
        const float4 z = {0.f, 0.f, 0.f, 0.f};
        ((float4*)g_ii)[t - nPfx] = z;               // row r==0
    } else if (t < nPfx + nRow0 + nCol0) {
        int k = t - nPfx - nRow0;
        int r = k / C4 + 1;
        int c4 = k & (C4 - 1);
        const float4 z = {0.f, 0.f, 0.f, 0.f};
        ((float4*)g_ii)[(r * WP) * C4 + c4] = z;     // col k==0
    }
}

// ---------------------------------------------------------------------------
// ROI pooling output. One block per box, one thread per channel.
// Full corner value = ii_partial(r,k) + rowPrefix(seg(k), r); 8 coalesced
// gathers per bin (rp side is L1/L2-resident). Output staged in smem,
// flushed with coalesced float4.
// ---------------------------------------------------------------------------
__global__ void __launch_bounds__(C) roi_kernel(const float* __restrict__ boxes,
                                                float* __restrict__ out)
{
    extern __shared__ float s_out[];                 // C*49 floats = 50176 B
    __shared__ int   s_rs[OH], s_re[OH], s_cs[OW], s_ce[OW];
    __shared__ int   s_csSeg[OW], s_ceSeg[OW];
    __shared__ float s_inv[OH * OW];

    const int n = blockIdx.x;
    const int c = threadIdx.x;

    if (c < OH) {
        const float sc = 0.25f;                      // 200/800, exact in fp32
        int bx1 = (int)floorf(boxes[n * 4 + 0] * sc);
        int by1 = (int)floorf(boxes[n * 4 + 1] * sc);
        int bx2 = (int)floorf(boxes[n * 4 + 2] * sc);
        int by2 = (int)floorf(boxes[n * 4 + 3] * sc);
        int x1 = min(max(bx1, 0), W - 1);
        int y1 = min(max(by1, 0), H - 1);
        int x2 = min(max(bx2 + 1, x1 + 1), W);
        int y2 = min(max(by2 + 1, y1 + 1), H);
        int rh = y2 - y1, rw = x2 - x1;
        int i = c;
        s_rs[i] = y1 + (i * rh) / OH;
        s_re[i] = y1 + ((i + 1) * rh + OH - 1) / OH;
        int csv = x1 + (i * rw) / OW;
        int cev = x1 + ((i + 1) * rw + OW - 1) / OW;
        s_cs[i] = csv;
        s_ce[i] = cev;
        s_csSeg[i] = max(csv - 1, 0) / LSEG;         // cs==0 -> seg0 (prefix 0)
        s_ceSeg[i] = (cev - 1) / LSEG;               // ce >= 1 always
    }
    __syncthreads();
    if (c < OH * OW) {
        int i = c / OW, j = c % OW;
        s_inv[c] = 1.0f / (float)((s_re[i] - s_rs[i]) * (s_ce[j] - s_cs[j]));
    }
    __syncthreads();

    const float* ii = g_ii + c;
    const float* rp = g_rowsum + c;

#pragma unroll
    for (int i = 0; i < OH; i++) {
        int rA = s_rs[i], rB = s_re[i];
#pragma unroll
        for (int j = 0; j < OW; j++) {
            int kA = s_cs[j],    kB = s_ce[j];
            int sA = s_csSeg[j], sB = s_ceSeg[j];
            float v = ii[(rB * WP + kB) * C] - ii[(rA * WP + kB) * C]
                    - ii[(rB * WP + kA) * C] + ii[(rA * WP + kA) * C]
                    + rp[(sB * HP + rB) * C] - rp[(sB * HP + rA) * C]
                    - rp[(sA * HP + rB) * C] + rp[(sA * HP + rA) * C];
            s_out[c * (OH * OW) + i * OW + j] = v * s_inv[i * OW + j];
        }
    }
    __syncthreads();

    // Coalesced float4 flush: 12544 floats = 3136 float4, base 16B-aligned.
    float4*       dst = (float4*)(out + (size_t)n * C * (OH * OW));
    const float4* src = (const float4*)s_out;
    for (int idx = c; idx < (C * OH * OW) / 4; idx += C)
        dst[idx] = src[idx];
}

// ---------------------------------------------------------------------------
extern "C" void kernel_launch(void* const* d_in, const int* in_sizes, int n_in,
                              void* d_out, int out_size)
{
    const float* fm    = (const float*)d_in[0];
    const float* boxes = (const float*)d_in[1];
    if (n_in >= 2 && in_sizes[0] < in_sizes[1]) {
        fm    = (const float*)d_in[1];
        boxes = (const float*)d_in[0];
    }
    float* out = (float*)d_out;

    // roi_kernel needs 50176 B dynamic smem (> 48 KB default)
    cudaFuncSetAttribute(roi_kernel, cudaFuncAttributeMaxDynamicSharedMemorySize,
                         C * OH * OW * (int)sizeof(float));

    // 1) fused transpose + segmented y-scan
    {
        dim3 grid((W + 31) / 32, C / 32, SEG);
        dim3 block(32, 8);
        yscan_kernel<<<grid, block>>>(fm);
    }
    // 2) y-segment exclusive prefix (float4)
    colprefix_kernel<<<(W * C4 + 255) / 256, 256>>>();
    // 3) segmented x-scan + fused y-fixup (float4)
    xscan_kernel<<<(SEG * H * C4) / 256, 256>>>();
    // 4) x-segment exclusive prefix + ii border zeroing (fused)
    {
        int total = HP * C4 + WP * C4 + H * C4;
        rowprefix_border_kernel<<<(total + 255) / 256, 256>>>();
    }
    // 5) ROI pooling output (x-fixup fused into gather)
    roi_kernel<<<NBOX, C, C * OH * OW * (int)sizeof(float)>>>(boxes, out);
}